// round 13
// baseline (speedup 1.0000x reference)
#include <cuda_runtime.h>

// Problem-fixed sizes (from setup_inputs)
#define BATCH 8
#define NH 778      // hand verts
#define FH 1538     // hand faces
#define NO 2000     // obj verts
#define FO 4000     // obj faces

#define TOLF    1e-7f
#define DETEPS  1e-8f   // float32(0.1 * TOL)
#define THRESH  25.0f
#define BIGF    3.4e38f

// Fixed ray direction (float32 of reference constants)
#define RDX 0.4395064455f
#define RDY 0.617598629942f
#define RDZ 0.652231566745f

// Raycast tiling
#define PT   4            // points per thread
#define RTPB 128          // threads per block
#define PPB  (PT*RTPB)    // 512 points per block
#define TCH  128          // triangles per smem stage (computed inline)
#define PB_O ((NO + PPB - 1) / PPB)   // 4
#define PB_H ((NH + PPB - 1) / PPB)   // 2
#define TB_O ((FH + TCH - 1) / TCH)   // 13
#define TB_H ((FO + TCH - 1) / TCH)   // 32
#define BLKS_O (BATCH * PB_O * TB_O)  // 416
#define BLKS_H (BATCH * PB_H * TB_H)  // 512

// Closest tiling: 4 queries/thread, 128-candidate chunk per block
#define CQB_H ((NH + PPB - 1) / PPB)  // 2
#define CQB_O ((NO + PPB - 1) / PPB)  // 4
#define CCH_O ((NO + TCH - 1) / TCH)  // 16
#define CCH_H ((NH + TCH - 1) / TCH)  // 7
#define CBLK_A (BATCH * CQB_H * CCH_O)  // 256
#define CBLK_B (BATCH * CQB_O * CCH_H)  // 224

// Reduction tiling
#define RSL   16
#define RITEMS (NH + NO)                         // 2778
#define RCH   ((RITEMS + RSL - 1) / RSL)         // 174
#define RBLKS (BATCH * RSL)                      // 128

// Scratch: per-chunk slots, every slot written unconditionally each launch
// (early-out blocks write neutral elements), so no zeroing pass is needed
// and replays are deterministic.
__device__ int   d_hits_o[BATCH * TB_O * NO];   // partial hit counts
__device__ int   d_hits_h[BATCH * TB_H * NH];
__device__ float d_best_h[BATCH * CCH_O * NH];  // partial min of d' = 0.5|c|^2 - q.c
__device__ float d_best_o[BATCH * CCH_H * NO];
__device__ float d_part[RBLKS * 6];
__device__ unsigned d_tick;                     // self-resetting ticket

// ---------------------------------------------------------------------------
// Parity raycast with INLINE triangle prep: each block computes its own
// 128-triangle affine forms into smem (1 tri/thread), then tests
// 512 points (4/thread) against them. Per-chunk counts -> slots (no atomics).
__global__ void raycast_fused(
        const float* __restrict__ hv, const int* __restrict__ hf,
        const float* __restrict__ ov, const int* __restrict__ of,
        const int* __restrict__ fsplits) {
    __shared__ float4 s[TCH * 3];
    int bid = blockIdx.x;
    const float* pts; const float* tverts; const int* tfaces;
    int* hslot; int P, t0, t1, pofs;
    if (bid < BLKS_O) {
        // obj points vs hand triangles (all valid)
        int b = bid / (PB_O * TB_O);
        int r = bid - b * (PB_O * TB_O);
        int pblk = r / TB_O, tcb = r - pblk * TB_O;
        pts    = ov + (size_t)b * NO * 3;  P = NO;
        tverts = hv + (size_t)b * NH * 3;
        tfaces = hf + (size_t)b * FH * 3;
        hslot  = d_hits_o + ((size_t)b * TB_O + tcb) * NO;
        t0 = tcb * TCH; t1 = min(t0 + TCH, FH);
        pofs = pblk * PPB;
    } else {
        // hand points vs obj triangles (valid prefix fsplits[b])
        int r2 = bid - BLKS_O;
        int b = r2 / (PB_H * TB_H);
        int r = r2 - b * (PB_H * TB_H);
        int pblk = r / TB_H, tcb = r - pblk * TB_H;
        pts    = hv + (size_t)b * NH * 3;  P = NH;
        tverts = ov + (size_t)b * NO * 3;
        tfaces = of + (size_t)b * FO * 3;
        hslot  = d_hits_h + ((size_t)b * TB_H + tcb) * NH;
        int lim = fsplits[b];
        t0 = tcb * TCH; t1 = min(t0 + TCH, lim);
        pofs = pblk * PPB;
        if (t0 >= t1) {
            // dead chunk: write neutral zeros for our points, done
            #pragma unroll
            for (int k = 0; k < PT; k++) {
                int p = pofs + k * RTPB + threadIdx.x;
                if (p < P) hslot[p] = 0;
            }
            return;
        }
    }

    // ---- inline triangle prep (one triangle per thread) ----
    int n = t1 - t0;
    if (threadIdx.x < n) {
        int tri = t0 + threadIdx.x;
        const int* fc = tfaces + (size_t)tri * 3;
        int i0 = fc[0], i1 = fc[1], i2 = fc[2];
        float v0x = tverts[i0*3+0], v0y = tverts[i0*3+1], v0z = tverts[i0*3+2];
        float v1x = tverts[i1*3+0], v1y = tverts[i1*3+1], v1z = tverts[i1*3+2];
        float v2x = tverts[i2*3+0], v2y = tverts[i2*3+1], v2z = tverts[i2*3+2];
        float e1x = v1x - v0x, e1y = v1y - v0y, e1z = v1z - v0z;
        float e2x = v2x - v0x, e2y = v2y - v0y, e2z = v2z - v0z;
        float pvx = RDY * e2z - RDZ * e2y;
        float pvy = RDZ * e2x - RDX * e2z;
        float pvz = RDX * e2y - RDY * e2x;
        float det = e1x * pvx + e1y * pvy + e1z * pvz;
        bool ok = fabsf(det) >= TOLF;
        float inv = ok ? 1.0f / (det + DETEPS) : 0.0f;
        float nux = pvx * inv, nuy = pvy * inv, nuz = pvz * inv;
        float cu = v0x * nux + v0y * nuy + v0z * nuz;
        float wx = e1y * RDZ - e1z * RDY;
        float wy = e1z * RDX - e1x * RDZ;
        float wz = e1x * RDY - e1y * RDX;
        float nvx = wx * inv, nvy = wy * inv, nvz = wz * inv;
        float cv = v0x * nvx + v0y * nvy + v0z * nvz;
        float gx = e1y * e2z - e1z * e2y;
        float gy = e1z * e2x - e1x * e2z;
        float gz = e1x * e2y - e1y * e2x;
        float ntx = gx * inv, nty = gy * inv, ntz = gz * inv;
        float ct = v0x * ntx + v0y * nty + v0z * ntz + TOLF;  // TOLF folded in
        s[threadIdx.x*3+0] = make_float4(nux, nuy, nuz, cu);
        s[threadIdx.x*3+1] = make_float4(nvx, nvy, nvz, cv);
        s[threadIdx.x*3+2] = make_float4(ntx, nty, ntz, ct);
    }

    float px[PT], py[PT], pz[PT];
    int cnt[PT]; bool act[PT];
    #pragma unroll
    for (int k = 0; k < PT; k++) {
        int p = pofs + k * RTPB + threadIdx.x;
        act[k] = p < P;
        int pc = act[k] ? p : 0;
        px[k] = pts[pc*3+0]; py[k] = pts[pc*3+1]; pz[k] = pts[pc*3+2];
        cnt[k] = 0;
    }
    __syncthreads();

    for (int j = 0; j < n; j++) {
        float4 q0 = s[j*3+0], q1 = s[j*3+1], q2 = s[j*3+2];
        #pragma unroll
        for (int k = 0; k < PT; k++) {
            float u = fmaf(pz[k], q0.z, fmaf(py[k], q0.y, fmaf(px[k], q0.x, -q0.w)));
            float v = fmaf(pz[k], q1.z, fmaf(py[k], q1.y, fmaf(px[k], q1.x, -q1.w)));
            float t = fmaf(pz[k], q2.z, fmaf(py[k], q2.y, fmaf(px[k], q2.x, -q2.w)));
            float m = fminf(fminf(u, v), t);           // all must be > 0
            float m2 = fminf(m, 1.0f - (u + v));       // and u+v < 1
            cnt[k] += (m2 > 0.0f) ? 1 : 0;             // parallel tris: u=v=0 -> miss
        }
    }
    #pragma unroll
    for (int k = 0; k < PT; k++) {
        int p = pofs + k * RTPB + threadIdx.x;
        if (act[k]) hslot[p] = cnt[k];                 // plain store, own slot
    }
}

// ---------------------------------------------------------------------------
// Nearest neighbor, both directions, register-tiled (4 queries/thread),
// min over metric d' = 0.5|c|^2 - q.c. Per-chunk minima -> slots.
__global__ __launch_bounds__(RTPB) void closest_fused(
        const float* __restrict__ hv, const float* __restrict__ ov,
        const int* __restrict__ vsplit) {
    __shared__ float4 s[TCH];
    int cb = blockIdx.x;
    const float* qpts; const float* cpts;
    float* slot; int Q, qofs, c0, c1;
    if (cb < CBLK_A) {
        // hand queries vs valid obj candidates
        int b = cb / (CQB_H * CCH_O);
        int r = cb - b * (CQB_H * CCH_O);
        int qb = r / CCH_O, ck = r - qb * CCH_O;
        int S = vsplit[b];
        c0 = ck * TCH; c1 = min(c0 + TCH, S);
        qpts = hv + (size_t)b * NH * 3; Q = NH;
        cpts = ov + (size_t)b * NO * 3;
        slot = d_best_h + ((size_t)b * CCH_O + ck) * NH;
        qofs = qb * PPB;
        if (c0 >= c1) {
            #pragma unroll
            for (int k = 0; k < PT; k++) {
                int q = qofs + k * RTPB + threadIdx.x;
                if (q < Q) slot[q] = BIGF;             // neutral element
            }
            return;
        }
    } else {
        // obj queries vs all hand candidates (all chunks valid)
        int r2 = cb - CBLK_A;
        int b = r2 / (CQB_O * CCH_H);
        int r = r2 - b * (CQB_O * CCH_H);
        int qb = r / CCH_H, ck = r - qb * CCH_H;
        c0 = ck * TCH; c1 = min(c0 + TCH, NH);
        qpts = ov + (size_t)b * NO * 3; Q = NO;
        cpts = hv + (size_t)b * NH * 3;
        slot = d_best_o + ((size_t)b * CCH_H + ck) * NO;
        qofs = qb * PPB;
    }
    float qx[PT], qy[PT], qz[PT], bst[PT];
    #pragma unroll
    for (int k = 0; k < PT; k++) {
        int q = qofs + k * RTPB + threadIdx.x;
        int qc = (q < Q) ? q : 0;
        qx[k] = -qpts[qc*3+0]; qy[k] = -qpts[qc*3+1]; qz[k] = -qpts[qc*3+2];
        bst[k] = BIGF;
    }
    int cntc = c1 - c0;
    if (threadIdx.x < cntc) {
        const float* c = cpts + (size_t)(c0 + threadIdx.x) * 3;
        float cx = c[0], cy = c[1], cz = c[2];
        s[threadIdx.x] = make_float4(cx, cy, cz, 0.5f*(cx*cx + cy*cy + cz*cz));
    }
    __syncthreads();
    for (int j = 0; j < cntc; j++) {
        float4 c = s[j];
        #pragma unroll
        for (int k = 0; k < PT; k++) {
            float d = fmaf(qz[k], c.z, fmaf(qy[k], c.y, fmaf(qx[k], c.x, c.w)));
            bst[k] = fminf(bst[k], d);
        }
    }
    #pragma unroll
    for (int k = 0; k < PT; k++) {
        int q = qofs + k * RTPB + threadIdx.x;
        if (q < Q) slot[q] = bst[k];                   // plain store, own slot
    }
}

// ---------------------------------------------------------------------------
// Reduction: 16 slices/batch. Each element folds its per-chunk slots
// (sum for parity, min for distance), computes tanh value, block-reduces,
// writes its own d_part slot; ticketed last block combines everything.
__global__ void reduce_all(const float* __restrict__ hv,
                           const float* __restrict__ ov,
                           const int* __restrict__ vsplit,
                           float* __restrict__ out) {
    __shared__ float sm[8][6];
    __shared__ float fin[BATCH][6];
    __shared__ int last;
    int b  = blockIdx.x / RSL;
    int sl = blockIdx.x - b * RSL;
    int i0 = sl * RCH, i1 = min(i0 + RCH, RITEMS);
    int S = vsplit[b];
    float s1 = 0, c1 = 0, s2 = 0, c2 = 0, s3 = 0, c3 = 0;
    for (int i = i0 + threadIdx.x; i < i1; i += blockDim.x) {
        if (i < NH) {
            int n = i;
            int hsum = 0;
            #pragma unroll
            for (int c = 0; c < TB_H; c++)
                hsum += d_hits_h[((size_t)b * TB_H + c) * NH + n];
            float dp = BIGF;
            #pragma unroll
            for (int c = 0; c < CCH_O; c++)
                dp = fminf(dp, d_best_h[((size_t)b * CCH_O + c) * NH + n]);
            const float* h = hv + ((size_t)b * NH + n) * 3;
            float rx = h[0]*h[0] + h[1]*h[1] + h[2]*h[2];
            float a = sqrtf(fmaxf(fmaf(2.0f, dp, rx), 0.0f));
            float v = THRESH * tanhf(a / THRESH);
            if ((hsum & 1) == 0) { s1 += v; c1 += 1.f; }
            else                 { s2 += v; c2 += 1.f; }
        } else {
            int m = i - NH;
            if (m < S) {
                int hsum = 0;
                #pragma unroll
                for (int c = 0; c < TB_O; c++)
                    hsum += d_hits_o[((size_t)b * TB_O + c) * NO + m];
                if (hsum & 1) {
                    float dp = BIGF;
                    #pragma unroll
                    for (int c = 0; c < CCH_H; c++)
                        dp = fminf(dp, d_best_o[((size_t)b * CCH_H + c) * NO + m]);
                    const float* o = ov + ((size_t)b * NO + m) * 3;
                    float ry = o[0]*o[0] + o[1]*o[1] + o[2]*o[2];
                    float a = sqrtf(fmaxf(fmaf(2.0f, dp, ry), 0.0f));
                    s3 += THRESH * tanhf(a / THRESH); c3 += 1.f;
                }
            }
        }
    }
    #pragma unroll
    for (int off = 16; off; off >>= 1) {
        s1 += __shfl_down_sync(0xffffffffu, s1, off);
        c1 += __shfl_down_sync(0xffffffffu, c1, off);
        s2 += __shfl_down_sync(0xffffffffu, s2, off);
        c2 += __shfl_down_sync(0xffffffffu, c2, off);
        s3 += __shfl_down_sync(0xffffffffu, s3, off);
        c3 += __shfl_down_sync(0xffffffffu, c3, off);
    }
    int w = threadIdx.x >> 5;
    if ((threadIdx.x & 31) == 0) {
        sm[w][0] = s1; sm[w][1] = c1; sm[w][2] = s2;
        sm[w][3] = c2; sm[w][4] = s3; sm[w][5] = c3;
    }
    __syncthreads();
    if (threadIdx.x == 0) {
        for (int i = 1; i < (int)(blockDim.x >> 5); i++) {
            s1 += sm[i][0]; c1 += sm[i][1]; s2 += sm[i][2];
            c2 += sm[i][3]; s3 += sm[i][4]; c3 += sm[i][5];
        }
        float* p = d_part + (size_t)blockIdx.x * 6;
        p[0] = s1; p[1] = c1; p[2] = s2; p[3] = c2; p[4] = s3; p[5] = c3;
        __threadfence();
        unsigned t = atomicAdd(&d_tick, 1u);
        last = (t == RBLKS - 1);
    }
    __syncthreads();
    if (last) {
        // cooperative final combine: thread (bb*6+comp) sums its column
        int t = threadIdx.x;
        if (t < BATCH * 6) {
            int bb = t / 6, comp = t - bb * 6;
            float ssum = 0.0f;
            #pragma unroll
            for (int s = 0; s < RSL; s++)
                ssum += d_part[(size_t)(bb * RSL + s) * 6 + comp];
            fin[bb][comp] = ssum;
        }
        __syncthreads();
        if (t < BATCH) {
            float p1 = fin[t][1], p3 = fin[t][3], p5 = fin[t][5];
            float missed_b = (p1 > 0.f) ? fin[t][0] / fmaxf(p1, 1.0f) : 0.0f;
            float ph_b     = (p3 > 0.f) ? fin[t][2] / fmaxf(p3, 1.0f) : 0.0f;
            float po_b     = (p5 > 0.f) ? fin[t][4] / fmaxf(p5, 1.0f) : 0.0f;
            out[2 + t]  = missed_b;
            out[10 + t] = ph_b + po_b;
        }
        if (t == 0) {
            float Sm = 0, Cm = 0, Sh = 0, Ch = 0, So = 0, Co = 0;
            #pragma unroll
            for (int bb = 0; bb < BATCH; bb++) {
                Sm += fin[bb][0]; Cm += fin[bb][1];
                Sh += fin[bb][2]; Ch += fin[bb][3];
                So += fin[bb][4]; Co += fin[bb][5];
            }
            float missed_loss = (Cm > 0.f) ? Sm / fmaxf(Cm, 1.0f) : 0.0f;
            float ph_loss     = (Ch > 0.f) ? Sh / fmaxf(Ch, 1.0f) : 0.0f;
            float po_loss     = (Co > 0.f) ? So / fmaxf(Co, 1.0f) : 0.0f;
            out[0] = missed_loss;
            out[1] = ph_loss + po_loss;
            d_tick = 0;                       // self-reset for next replay
        }
    }
}

// ---------------------------------------------------------------------------
extern "C" void kernel_launch(void* const* d_in, const int* in_sizes, int n_in,
                              void* d_out, int out_size) {
    const float* hand_verts = (const float*)d_in[0];
    const int*   hand_faces = (const int*)d_in[1];
    const float* obj_verts  = (const float*)d_in[2];
    const int*   obj_faces  = (const int*)d_in[3];
    const int*   vsplits    = (const int*)d_in[4];
    const int*   fsplits    = (const int*)d_in[5];
    float* out = (float*)d_out;

    raycast_fused<<<BLKS_O + BLKS_H, RTPB>>>(
        hand_verts, hand_faces, obj_verts, obj_faces, fsplits);
    closest_fused<<<CBLK_A + CBLK_B, RTPB>>>(hand_verts, obj_verts, vsplits);
    reduce_all<<<RBLKS, 256>>>(hand_verts, obj_verts, vsplits, out);
}

// round 14
// speedup vs baseline: 1.1248x; 1.1248x over previous
#include <cuda_runtime.h>

// Problem-fixed sizes (from setup_inputs)
#define BATCH 8
#define NH 778      // hand verts
#define FH 1538     // hand faces
#define NO 2000     // obj verts
#define FO 4000     // obj faces

#define TOLF    1e-7f
#define DETEPS  1e-8f   // float32(0.1 * TOL)
#define THRESH  25.0f
#define BIGF    3.4e38f

// Fixed ray direction (float32 of reference constants)
#define RDX 0.4395064455f
#define RDY 0.617598629942f
#define RDZ 0.652231566745f

// Raycast tiling
#define PT   4            // points per thread (2 packed pairs)
#define RTPB 128          // threads per block
#define PPB  (PT*RTPB)    // 512 points per block
#define TCH  128          // triangles per smem stage
#define PB_O ((NO + PPB - 1) / PPB)   // 4
#define PB_H ((NH + PPB - 1) / PPB)   // 2
#define TB_O ((FH + TCH - 1) / TCH)   // 13
#define TB_H ((FO + TCH - 1) / TCH)   // 32
#define BLKS_O (BATCH * PB_O * TB_O)  // 416
#define BLKS_H (BATCH * PB_H * TB_H)  // 512

// Closest tiling
#define CQB_H ((NH + PPB - 1) / PPB)  // 2
#define CQB_O ((NO + PPB - 1) / PPB)  // 4
#define CCH_O ((NO + TCH - 1) / TCH)  // 16
#define CCH_H ((NH + TCH - 1) / TCH)  // 7
#define CBLK_A (BATCH * CQB_H * CCH_O)  // 256
#define CBLK_B (BATCH * CQB_O * CCH_H)  // 224

// Reduction tiling
#define RSL   16
#define RITEMS (NH + NO)                         // 2778
#define RCH   ((RITEMS + RSL - 1) / RSL)         // 174
#define RBLKS (BATCH * RSL)                      // 128

typedef unsigned long long u64;

// Scratch (no allocations allowed)
// Triangle data pre-splatted for f32x2: 6 float4 per triangle:
//  [0]=(nux,nux,nuy,nuy) [1]=(nuz,nuz,-cu,-cu)
//  [2]=(nvx,nvx,nvy,nvy) [3]=(nvz,nvz,-cv,-cv)
//  [4]=(ntx,ntx,nty,nty) [5]=(ntz,ntz,-ct',-ct')   (ct' has TOLF folded in)
__device__ float4   d_htri[BATCH * FH * 6];
__device__ float4   d_otri[BATCH * FO * 6];
__device__ unsigned d_hits_o[BATCH * NO];   // MSB = hit parity
__device__ unsigned d_hits_h[BATCH * NH];
__device__ unsigned d_best_h[BATCH * NH];   // orderable-uint of min d'
__device__ unsigned d_best_o[BATCH * NO];
__device__ float    d_part[BATCH * 6];
__device__ unsigned d_tick;

// ---- f32x2 packed helpers (sm_100+ PTX) -----------------------------------
__device__ __forceinline__ u64 pk2(float lo, float hi) {
    u64 r; asm("mov.b64 %0, {%1, %2};" : "=l"(r) : "f"(lo), "f"(hi)); return r;
}
__device__ __forceinline__ void upk2u(u64 v, unsigned &lo, unsigned &hi) {
    asm("mov.b64 {%0, %1}, %2;" : "=r"(lo), "=r"(hi) : "l"(v));
}
__device__ __forceinline__ void upk2f(u64 v, float &lo, float &hi) {
    asm("mov.b64 {%0, %1}, %2;" : "=f"(lo), "=f"(hi) : "l"(v));
}
__device__ __forceinline__ u64 fma2(u64 a, u64 b, u64 c) {
    u64 d; asm("fma.rn.f32x2 %0, %1, %2, %3;" : "=l"(d) : "l"(a), "l"(b), "l"(c));
    return d;
}
__device__ __forceinline__ u64 add2(u64 a, u64 b) {
    u64 d; asm("add.rn.f32x2 %0, %1, %2;" : "=l"(d) : "l"(a), "l"(b)); return d;
}

__device__ __forceinline__ unsigned ford(float f) {
    unsigned u = __float_as_uint(f);
    return (u & 0x80000000u) ? ~u : (u | 0x80000000u);
}
__device__ __forceinline__ float funord(unsigned k) {
    unsigned u = (k & 0x80000000u) ? (k & 0x7fffffffu) : ~k;
    return __uint_as_float(u);
}

// ---------------------------------------------------------------------------
// Triangle affine forms, pre-splatted; invalid/parallel -> zero coeffs with
// -ct' = -TOLF so t' < 0 -> guaranteed miss (matches reference mask).
__device__ __forceinline__ void prep_one(int i,
        const float* __restrict__ hv, const int* __restrict__ hf,
        const float* __restrict__ ov, const int* __restrict__ of,
        const int* __restrict__ fsplits) {
    const float* verts; const int* faces; float4* out;
    bool extra_valid = true;
    if (i < BATCH * FH) {
        int b = i / FH;
        verts = hv + (size_t)b * NH * 3;
        faces = hf + (size_t)i * 3;
        out   = d_htri + (size_t)i * 6;
    } else {
        int j = i - BATCH * FH;
        if (j >= BATCH * FO) return;
        int b = j / FO, f = j - b * FO;
        verts = ov + (size_t)b * NO * 3;
        faces = of + (size_t)j * 3;
        out   = d_otri + (size_t)j * 6;
        extra_valid = (f < fsplits[b]);
    }
    int i0 = faces[0], i1 = faces[1], i2 = faces[2];
    float v0x = verts[i0*3+0], v0y = verts[i0*3+1], v0z = verts[i0*3+2];
    float v1x = verts[i1*3+0], v1y = verts[i1*3+1], v1z = verts[i1*3+2];
    float v2x = verts[i2*3+0], v2y = verts[i2*3+1], v2z = verts[i2*3+2];
    float e1x = v1x - v0x, e1y = v1y - v0y, e1z = v1z - v0z;
    float e2x = v2x - v0x, e2y = v2y - v0y, e2z = v2z - v0z;
    float pvx = RDY * e2z - RDZ * e2y;
    float pvy = RDZ * e2x - RDX * e2z;
    float pvz = RDX * e2y - RDY * e2x;
    float det = e1x * pvx + e1y * pvy + e1z * pvz;
    bool ok = (fabsf(det) >= TOLF) && extra_valid;
    float inv = ok ? 1.0f / (det + DETEPS) : 0.0f;
    float nux = pvx * inv, nuy = pvy * inv, nuz = pvz * inv;
    float cu = v0x * nux + v0y * nuy + v0z * nuz;
    float wx = e1y * RDZ - e1z * RDY;
    float wy = e1z * RDX - e1x * RDZ;
    float wz = e1x * RDY - e1y * RDX;
    float nvx = wx * inv, nvy = wy * inv, nvz = wz * inv;
    float cv = v0x * nvx + v0y * nvy + v0z * nvz;
    float gx = e1y * e2z - e1z * e2y;
    float gy = e1z * e2x - e1x * e2z;
    float gz = e1x * e2y - e1y * e2x;
    float ntx = gx * inv, nty = gy * inv, ntz = gz * inv;
    float ct = v0x * ntx + v0y * nty + v0z * ntz + TOLF;  // TOLF folded in
    out[0] = make_float4(nux, nux, nuy, nuy);
    out[1] = make_float4(nuz, nuz, -cu, -cu);
    out[2] = make_float4(nvx, nvx, nvy, nvy);
    out[3] = make_float4(nvz, nvz, -cv, -cv);
    out[4] = make_float4(ntx, ntx, nty, nty);
    out[5] = make_float4(ntz, ntz, -ct, -ct);
}

// Prep: 2 triangles per thread + all scratch zeroing.
__global__ void prep_fused(const float* __restrict__ hv, const int* __restrict__ hf,
                           const float* __restrict__ ov, const int* __restrict__ of,
                           const int* __restrict__ fsplits) {
    int tid = blockIdx.x * blockDim.x + threadIdx.x;
    if (tid < BATCH * NO) { d_hits_o[tid] = 0u; d_best_o[tid] = 0xffffffffu; }
    if (tid < BATCH * NH) { d_hits_h[tid] = 0u; d_best_h[tid] = 0xffffffffu; }
    if (tid < BATCH * 6)  d_part[tid] = 0.0f;
    if (tid == 0) d_tick = 0;
    int i0 = tid * 2;
    prep_one(i0,     hv, hf, ov, of, fsplits);
    prep_one(i0 + 1, hv, hf, ov, of, fsplits);
}

// ---------------------------------------------------------------------------
// Parity raycast, packed f32x2: 2 point-pairs per thread, sign-bit OR for the
// hit test, LOP3 parity accumulation, atomicXor publish.
__global__ void raycast_fused(
        const float* __restrict__ hv, const float* __restrict__ ov,
        const int* __restrict__ fsplits) {
    __shared__ float4 s[TCH * 6];
    int bid = blockIdx.x;
    const float* pts; const float4* tb; unsigned* hits;
    int P, t0, t1, pofs;
    if (bid < BLKS_O) {
        int b = bid / (PB_O * TB_O);
        int r = bid - b * (PB_O * TB_O);
        int pblk = r / TB_O, tcb = r - pblk * TB_O;
        pts  = ov + (size_t)b * NO * 3;  P = NO;
        tb   = d_htri + (size_t)b * FH * 6;
        hits = d_hits_o + b * NO;
        t0 = tcb * TCH; t1 = min(t0 + TCH, FH);
        pofs = pblk * PPB;
    } else {
        int r2 = bid - BLKS_O;
        int b = r2 / (PB_H * TB_H);
        int r = r2 - b * (PB_H * TB_H);
        int pblk = r / TB_H, tcb = r - pblk * TB_H;
        pts  = hv + (size_t)b * NH * 3;  P = NH;
        tb   = d_otri + (size_t)b * FO * 6;
        hits = d_hits_h + b * NH;
        int lim = fsplits[b];                 // invalid tail is contiguous
        t0 = tcb * TCH; t1 = min(t0 + TCH, lim);
        pofs = pblk * PPB;
        if (t0 >= t1) return;                 // XOR identity: nothing to publish
    }

    int n = t1 - t0;
    if (threadIdx.x < n) {
        const float4* src = tb + (size_t)(t0 + threadIdx.x) * 6;
        #pragma unroll
        for (int q = 0; q < 6; q++) s[threadIdx.x*6+q] = src[q];
    }

    float px[PT], py[PT], pz[PT];
    bool act[PT];
    #pragma unroll
    for (int k = 0; k < PT; k++) {
        int p = pofs + k * RTPB + threadIdx.x;
        act[k] = p < P;
        int pc = act[k] ? p : 0;
        px[k] = pts[pc*3+0]; py[k] = pts[pc*3+1]; pz[k] = pts[pc*3+2];
    }
    u64 pxp[2], pyp[2], pzp[2];
    pxp[0] = pk2(px[0], px[1]); pxp[1] = pk2(px[2], px[3]);
    pyp[0] = pk2(py[0], py[1]); pyp[1] = pk2(py[2], py[3]);
    pzp[0] = pk2(pz[0], pz[1]); pzp[1] = pk2(pz[2], pz[3]);
    const u64 ONE2  = pk2(1.0f, 1.0f);
    const u64 NEG2  = pk2(-1.0f, -1.0f);
    unsigned cnt[PT] = {0u, 0u, 0u, 0u};
    __syncthreads();

    const ulonglong2* sd = (const ulonglong2*)s;
    for (int j = 0; j < n; j++) {
        ulonglong2 A = sd[j*6+0], B = sd[j*6+1], C = sd[j*6+2];
        ulonglong2 D = sd[j*6+3], E = sd[j*6+4], F = sd[j*6+5];
        #pragma unroll
        for (int pr = 0; pr < 2; pr++) {
            u64 u = fma2(pzp[pr], B.x, B.y);
            u     = fma2(pyp[pr], A.y, u);
            u     = fma2(pxp[pr], A.x, u);
            u64 v = fma2(pzp[pr], D.x, D.y);
            v     = fma2(pyp[pr], C.y, v);
            v     = fma2(pxp[pr], C.x, v);
            u64 t = fma2(pzp[pr], F.x, F.y);
            t     = fma2(pyp[pr], E.y, t);
            t     = fma2(pxp[pr], E.x, t);
            u64 sm = add2(u, v);
            u64 w  = fma2(sm, NEG2, ONE2);       // 1 - (u+v)
            unsigned ul,uh,vl,vh,tl,th,wl,wh;
            upk2u(u,ul,uh); upk2u(v,vl,vh); upk2u(t,tl,th); upk2u(w,wl,wh);
            // hit iff all four sign bits clear; accumulate parity in MSB
            cnt[pr*2+0] ^= ~(ul | vl | tl | wl) & 0x80000000u;
            cnt[pr*2+1] ^= ~(uh | vh | th | wh) & 0x80000000u;
        }
    }
    #pragma unroll
    for (int k = 0; k < PT; k++) {
        if (act[k] && cnt[k])
            atomicXor(&hits[pofs + k * RTPB + threadIdx.x], cnt[k]);
    }
}

// ---------------------------------------------------------------------------
// Nearest neighbor, packed f32x2: candidates pre-splatted in smem,
// min over metric d' = 0.5|c|^2 - q.c.
__global__ __launch_bounds__(RTPB) void closest_fused(
        const float* __restrict__ hv, const float* __restrict__ ov,
        const int* __restrict__ vsplit) {
    __shared__ float4 s[TCH * 2];
    int cb = blockIdx.x;
    const float* qpts; const float* cpts;
    unsigned* best; int Q, qofs, c0, c1, Svalid;
    if (cb < CBLK_A) {
        // hand queries vs valid obj candidates
        int b = cb / (CQB_H * CCH_O);
        int r = cb - b * (CQB_H * CCH_O);
        int qb = r / CCH_O, ck = r - qb * CCH_O;
        int S = vsplit[b];
        c0 = ck * TCH; c1 = min(c0 + TCH, S);
        if (c0 >= c1) return;
        qpts = hv + (size_t)b * NH * 3; Q = NH; Svalid = NH;
        cpts = ov + (size_t)b * NO * 3;
        best = d_best_h + b * NH;
        qofs = qb * PPB;
    } else {
        // obj queries (valid only) vs all hand candidates
        int r2 = cb - CBLK_A;
        int b = r2 / (CQB_O * CCH_H);
        int r = r2 - b * (CQB_O * CCH_H);
        int qb = r / CCH_H, ck = r - qb * CCH_H;
        c0 = ck * TCH; c1 = min(c0 + TCH, NH);
        qpts = ov + (size_t)b * NO * 3; Q = NO; Svalid = vsplit[b];
        cpts = hv + (size_t)b * NH * 3;
        best = d_best_o + b * NO;
        qofs = qb * PPB;
    }
    int cntc = c1 - c0;
    if (threadIdx.x < cntc) {
        const float* c = cpts + (size_t)(c0 + threadIdx.x) * 3;
        float cx = c[0], cy = c[1], cz = c[2];
        float cw = 0.5f * (cx*cx + cy*cy + cz*cz);
        s[threadIdx.x*2+0] = make_float4(cx, cx, cy, cy);
        s[threadIdx.x*2+1] = make_float4(cz, cz, cw, cw);
    }

    float qx[PT], qy[PT], qz[PT], bst[PT];
    bool act[PT];
    #pragma unroll
    for (int k = 0; k < PT; k++) {
        int q = qofs + k * RTPB + threadIdx.x;
        act[k] = (q < Q) && (q < Svalid);
        int qc = (q < Q) ? q : 0;
        qx[k] = -qpts[qc*3+0]; qy[k] = -qpts[qc*3+1]; qz[k] = -qpts[qc*3+2];
        bst[k] = BIGF;
    }
    u64 qxp[2], qyp[2], qzp[2];
    qxp[0] = pk2(qx[0], qx[1]); qxp[1] = pk2(qx[2], qx[3]);
    qyp[0] = pk2(qy[0], qy[1]); qyp[1] = pk2(qy[2], qy[3]);
    qzp[0] = pk2(qz[0], qz[1]); qzp[1] = pk2(qz[2], qz[3]);
    __syncthreads();

    const ulonglong2* sc = (const ulonglong2*)s;
    for (int j = 0; j < cntc; j++) {
        ulonglong2 C0 = sc[j*2+0], C1 = sc[j*2+1];
        #pragma unroll
        for (int pr = 0; pr < 2; pr++) {
            u64 d = fma2(qzp[pr], C1.x, C1.y);
            d     = fma2(qyp[pr], C0.y, d);
            d     = fma2(qxp[pr], C0.x, d);
            float dl, dh; upk2f(d, dl, dh);
            bst[pr*2+0] = fminf(bst[pr*2+0], dl);
            bst[pr*2+1] = fminf(bst[pr*2+1], dh);
        }
    }
    #pragma unroll
    for (int k = 0; k < PT; k++) {
        if (act[k])
            atomicMin(&best[qofs + k * RTPB + threadIdx.x], ford(bst[k]));
    }
}

// ---------------------------------------------------------------------------
// Parallel reduction: 16 slices/batch, partials into d_part (atomicAdd);
// ticketed last block writes all 18 outputs.
__global__ void reduce_all(const float* __restrict__ hv,
                           const float* __restrict__ ov,
                           const int* __restrict__ vsplit,
                           float* __restrict__ out) {
    __shared__ float sm[8][6];
    int b  = blockIdx.x / RSL;
    int sl = blockIdx.x - b * RSL;
    int i0 = sl * RCH, i1 = min(i0 + RCH, RITEMS);
    int S = vsplit[b];
    float s1 = 0, c1 = 0, s2 = 0, c2 = 0, s3 = 0, c3 = 0;
    for (int i = i0 + threadIdx.x; i < i1; i += blockDim.x) {
        if (i < NH) {
            int n = i;
            const float* h = hv + ((size_t)b * NH + n) * 3;
            float rx = h[0]*h[0] + h[1]*h[1] + h[2]*h[2];
            float dp = funord(d_best_h[b * NH + n]);   // min(0.5*ry - zz)
            float a = sqrtf(fmaxf(fmaf(2.0f, dp, rx), 0.0f));
            float v = THRESH * tanhf(a / THRESH);
            bool ext = (d_hits_h[b * NH + n] & 0x80000000u) == 0;  // parity MSB
            if (ext) { s1 += v; c1 += 1.f; }
            else     { s2 += v; c2 += 1.f; }
        } else {
            int m = i - NH;
            if (m < S && (d_hits_o[b * NO + m] & 0x80000000u) != 0) {
                const float* o = ov + ((size_t)b * NO + m) * 3;
                float ry = o[0]*o[0] + o[1]*o[1] + o[2]*o[2];
                float dp = funord(d_best_o[b * NO + m]);
                float a = sqrtf(fmaxf(fmaf(2.0f, dp, ry), 0.0f));
                s3 += THRESH * tanhf(a / THRESH); c3 += 1.f;
            }
        }
    }
    #pragma unroll
    for (int off = 16; off; off >>= 1) {
        s1 += __shfl_down_sync(0xffffffffu, s1, off);
        c1 += __shfl_down_sync(0xffffffffu, c1, off);
        s2 += __shfl_down_sync(0xffffffffu, s2, off);
        c2 += __shfl_down_sync(0xffffffffu, c2, off);
        s3 += __shfl_down_sync(0xffffffffu, s3, off);
        c3 += __shfl_down_sync(0xffffffffu, c3, off);
    }
    int w = threadIdx.x >> 5;
    if ((threadIdx.x & 31) == 0) {
        sm[w][0] = s1; sm[w][1] = c1; sm[w][2] = s2;
        sm[w][3] = c2; sm[w][4] = s3; sm[w][5] = c3;
    }
    __syncthreads();
    if (threadIdx.x == 0) {
        for (int i = 1; i < (int)(blockDim.x >> 5); i++) {
            s1 += sm[i][0]; c1 += sm[i][1]; s2 += sm[i][2];
            c2 += sm[i][3]; s3 += sm[i][4]; c3 += sm[i][5];
        }
        atomicAdd(&d_part[b*6+0], s1); atomicAdd(&d_part[b*6+1], c1);
        atomicAdd(&d_part[b*6+2], s2); atomicAdd(&d_part[b*6+3], c2);
        atomicAdd(&d_part[b*6+4], s3); atomicAdd(&d_part[b*6+5], c3);
        __threadfence();
        unsigned t = atomicAdd(&d_tick, 1u);
        if (t == RBLKS - 1) {   // last block: all outputs
            float Sm = 0, Cm = 0, Sh = 0, Ch = 0, So = 0, Co = 0;
            for (int bb = 0; bb < BATCH; bb++) {
                float p0 = d_part[bb*6+0], p1 = d_part[bb*6+1];
                float p2 = d_part[bb*6+2], p3 = d_part[bb*6+3];
                float p4 = d_part[bb*6+4], p5 = d_part[bb*6+5];
                Sm += p0; Cm += p1; Sh += p2; Ch += p3; So += p4; Co += p5;
                float missed_b = (p1 > 0.f) ? p0 / fmaxf(p1, 1.0f) : 0.0f;
                float ph_b     = (p3 > 0.f) ? p2 / fmaxf(p3, 1.0f) : 0.0f;
                float po_b     = (p5 > 0.f) ? p4 / fmaxf(p5, 1.0f) : 0.0f;
                out[2 + bb]  = missed_b;
                out[10 + bb] = ph_b + po_b;
            }
            float missed_loss = (Cm > 0.f) ? Sm / fmaxf(Cm, 1.0f) : 0.0f;
            float ph_loss     = (Ch > 0.f) ? Sh / fmaxf(Ch, 1.0f) : 0.0f;
            float po_loss     = (Co > 0.f) ? So / fmaxf(Co, 1.0f) : 0.0f;
            out[0] = missed_loss;
            out[1] = ph_loss + po_loss;
        }
    }
}

// ---------------------------------------------------------------------------
extern "C" void kernel_launch(void* const* d_in, const int* in_sizes, int n_in,
                              void* d_out, int out_size) {
    const float* hand_verts = (const float*)d_in[0];
    const int*   hand_faces = (const int*)d_in[1];
    const float* obj_verts  = (const float*)d_in[2];
    const int*   obj_faces  = (const int*)d_in[3];
    const int*   vsplits    = (const int*)d_in[4];
    const int*   fsplits    = (const int*)d_in[5];
    float* out = (float*)d_out;

    prep_fused<<<(BATCH * (FH + FO) / 2 + 127) / 128, 128>>>(
        hand_verts, hand_faces, obj_verts, obj_faces, fsplits);
    raycast_fused<<<BLKS_O + BLKS_H, RTPB>>>(hand_verts, obj_verts, fsplits);
    closest_fused<<<CBLK_A + CBLK_B, RTPB>>>(hand_verts, obj_verts, vsplits);
    reduce_all<<<RBLKS, 256>>>(hand_verts, obj_verts, vsplits, out);
}

// round 15
// speedup vs baseline: 1.3163x; 1.1703x over previous
#include <cuda_runtime.h>

// Problem-fixed sizes (from setup_inputs)
#define BATCH 8
#define NH 778      // hand verts
#define FH 1538     // hand faces
#define NO 2000     // obj verts
#define FO 4000     // obj faces

#define TOLF    1e-7f
#define DETEPS  1e-8f   // float32(0.1 * TOL)
#define THRESH  25.0f
#define BIGF    3.4e38f

// Fixed ray direction (float32 of reference constants)
#define RDX 0.4395064455f
#define RDY 0.617598629942f
#define RDZ 0.652231566745f

// Raycast tiling
#define PT   4            // points per thread (2 packed pairs)
#define RTPB 128          // threads per block
#define PPB  (PT*RTPB)    // 512 points per block
#define TCH  64           // triangles per smem stage (smaller -> more blocks)
#define PB_O ((NO + PPB - 1) / PPB)   // 4
#define PB_H ((NH + PPB - 1) / PPB)   // 2
#define TB_O ((FH + TCH - 1) / TCH)   // 25
#define TB_H ((FO + TCH - 1) / TCH)   // 63
#define BLKS_O (BATCH * PB_O * TB_O)  // 800
#define BLKS_H (BATCH * PB_H * TB_H)  // 1008

// Closest tiling (unchanged, proven)
#define CTCH 128
#define CQB_H ((NH + PPB - 1) / PPB)  // 2
#define CQB_O ((NO + PPB - 1) / PPB)  // 4
#define CCH_O ((NO + CTCH - 1) / CTCH)  // 16
#define CCH_H ((NH + CTCH - 1) / CTCH)  // 7
#define CBLK_A (BATCH * CQB_H * CCH_O)  // 256
#define CBLK_B (BATCH * CQB_O * CCH_H)  // 224

// Reduction tiling
#define RSL   16
#define RITEMS (NH + NO)                         // 2778
#define RCH   ((RITEMS + RSL - 1) / RSL)         // 174
#define RBLKS (BATCH * RSL)                      // 128

typedef unsigned long long u64;

// Scratch (no allocations allowed)
// Triangle data pre-splatted for f32x2: 6 float4 per triangle:
//  [0]=(nux,nux,nuy,nuy) [1]=(nuz,nuz,-cu,-cu)
//  [2]=(nvx,nvx,nvy,nvy) [3]=(nvz,nvz,-cv,-cv)
//  [4]=(ntx,ntx,nty,nty) [5]=(ntz,ntz,-ct',-ct')   (ct' has TOLF folded in)
__device__ float4   d_htri[BATCH * FH * 6];
__device__ float4   d_otri[BATCH * FO * 6];
__device__ unsigned d_hits_o[BATCH * NO];   // MSB = hit parity
__device__ unsigned d_hits_h[BATCH * NH];
__device__ unsigned d_best_h[BATCH * NH];   // orderable-uint of min d'
__device__ unsigned d_best_o[BATCH * NO];
__device__ float    d_part[BATCH * 6];
__device__ unsigned d_tick;

// ---- f32x2 packed helpers (sm_100+ PTX) -----------------------------------
__device__ __forceinline__ u64 pk2(float lo, float hi) {
    u64 r; asm("mov.b64 %0, {%1, %2};" : "=l"(r) : "f"(lo), "f"(hi)); return r;
}
__device__ __forceinline__ void upk2u(u64 v, unsigned &lo, unsigned &hi) {
    asm("mov.b64 {%0, %1}, %2;" : "=r"(lo), "=r"(hi) : "l"(v));
}
__device__ __forceinline__ void upk2f(u64 v, float &lo, float &hi) {
    asm("mov.b64 {%0, %1}, %2;" : "=f"(lo), "=f"(hi) : "l"(v));
}
__device__ __forceinline__ u64 fma2(u64 a, u64 b, u64 c) {
    u64 d; asm("fma.rn.f32x2 %0, %1, %2, %3;" : "=l"(d) : "l"(a), "l"(b), "l"(c));
    return d;
}
__device__ __forceinline__ u64 add2(u64 a, u64 b) {
    u64 d; asm("add.rn.f32x2 %0, %1, %2;" : "=l"(d) : "l"(a), "l"(b)); return d;
}

__device__ __forceinline__ unsigned ford(float f) {
    unsigned u = __float_as_uint(f);
    return (u & 0x80000000u) ? ~u : (u | 0x80000000u);
}
__device__ __forceinline__ float funord(unsigned k) {
    unsigned u = (k & 0x80000000u) ? (k & 0x7fffffffu) : ~k;
    return __uint_as_float(u);
}

// Fast 25*tanh(a/25): branch-free MUFU path; a in [0, ~30] here so no overflow.
__device__ __forceinline__ float val25(float a) {
    float x = a * (1.0f / THRESH);
    float e = __expf(x + x);
    return THRESH * __fdividef(e - 1.0f, e + 1.0f);
}

// ---------------------------------------------------------------------------
// Triangle affine forms, pre-splatted; invalid/parallel -> zero coeffs with
// -ct' = -TOLF so t' < 0 -> guaranteed miss (matches reference mask).
__device__ __forceinline__ void prep_one(int i,
        const float* __restrict__ hv, const int* __restrict__ hf,
        const float* __restrict__ ov, const int* __restrict__ of,
        const int* __restrict__ fsplits) {
    const float* verts; const int* faces; float4* out;
    bool extra_valid = true;
    if (i < BATCH * FH) {
        int b = i / FH;
        verts = hv + (size_t)b * NH * 3;
        faces = hf + (size_t)i * 3;
        out   = d_htri + (size_t)i * 6;
    } else {
        int j = i - BATCH * FH;
        if (j >= BATCH * FO) return;
        int b = j / FO, f = j - b * FO;
        verts = ov + (size_t)b * NO * 3;
        faces = of + (size_t)j * 3;
        out   = d_otri + (size_t)j * 6;
        extra_valid = (f < fsplits[b]);
    }
    int i0 = faces[0], i1 = faces[1], i2 = faces[2];
    float v0x = verts[i0*3+0], v0y = verts[i0*3+1], v0z = verts[i0*3+2];
    float v1x = verts[i1*3+0], v1y = verts[i1*3+1], v1z = verts[i1*3+2];
    float v2x = verts[i2*3+0], v2y = verts[i2*3+1], v2z = verts[i2*3+2];
    float e1x = v1x - v0x, e1y = v1y - v0y, e1z = v1z - v0z;
    float e2x = v2x - v0x, e2y = v2y - v0y, e2z = v2z - v0z;
    float pvx = RDY * e2z - RDZ * e2y;
    float pvy = RDZ * e2x - RDX * e2z;
    float pvz = RDX * e2y - RDY * e2x;
    float det = e1x * pvx + e1y * pvy + e1z * pvz;
    bool ok = (fabsf(det) >= TOLF) && extra_valid;
    float inv = ok ? 1.0f / (det + DETEPS) : 0.0f;
    float nux = pvx * inv, nuy = pvy * inv, nuz = pvz * inv;
    float cu = v0x * nux + v0y * nuy + v0z * nuz;
    float wx = e1y * RDZ - e1z * RDY;
    float wy = e1z * RDX - e1x * RDZ;
    float wz = e1x * RDY - e1y * RDX;
    float nvx = wx * inv, nvy = wy * inv, nvz = wz * inv;
    float cv = v0x * nvx + v0y * nvy + v0z * nvz;
    float gx = e1y * e2z - e1z * e2y;
    float gy = e1z * e2x - e1x * e2z;
    float gz = e1x * e2y - e1y * e2x;
    float ntx = gx * inv, nty = gy * inv, ntz = gz * inv;
    float ct = v0x * ntx + v0y * nty + v0z * ntz + TOLF;  // TOLF folded in
    out[0] = make_float4(nux, nux, nuy, nuy);
    out[1] = make_float4(nuz, nuz, -cu, -cu);
    out[2] = make_float4(nvx, nvx, nvy, nvy);
    out[3] = make_float4(nvz, nvz, -cv, -cv);
    out[4] = make_float4(ntx, ntx, nty, nty);
    out[5] = make_float4(ntz, ntz, -ct, -ct);
}

// Prep: 2 triangles per thread + all scratch zeroing.
__global__ void prep_fused(const float* __restrict__ hv, const int* __restrict__ hf,
                           const float* __restrict__ ov, const int* __restrict__ of,
                           const int* __restrict__ fsplits) {
    int tid = blockIdx.x * blockDim.x + threadIdx.x;
    if (tid < BATCH * NO) { d_hits_o[tid] = 0u; d_best_o[tid] = 0xffffffffu; }
    if (tid < BATCH * NH) { d_hits_h[tid] = 0u; d_best_h[tid] = 0xffffffffu; }
    if (tid < BATCH * 6)  d_part[tid] = 0.0f;
    if (tid == 0) d_tick = 0;
    int i0 = tid * 2;
    prep_one(i0,     hv, hf, ov, of, fsplits);
    prep_one(i0 + 1, hv, hf, ov, of, fsplits);
}

// ---------------------------------------------------------------------------
// Parity raycast, packed f32x2: 2 point-pairs per thread, sign-bit OR for the
// hit test, LOP3 parity accumulation, atomicXor publish. TCH=64 for occupancy.
__global__ void raycast_fused(
        const float* __restrict__ hv, const float* __restrict__ ov,
        const int* __restrict__ fsplits) {
    __shared__ float4 s[TCH * 6];
    int bid = blockIdx.x;
    const float* pts; const float4* tb; unsigned* hits;
    int P, t0, t1, pofs;
    if (bid < BLKS_O) {
        int b = bid / (PB_O * TB_O);
        int r = bid - b * (PB_O * TB_O);
        int pblk = r / TB_O, tcb = r - pblk * TB_O;
        pts  = ov + (size_t)b * NO * 3;  P = NO;
        tb   = d_htri + (size_t)b * FH * 6;
        hits = d_hits_o + b * NO;
        t0 = tcb * TCH; t1 = min(t0 + TCH, FH);
        pofs = pblk * PPB;
    } else {
        int r2 = bid - BLKS_O;
        int b = r2 / (PB_H * TB_H);
        int r = r2 - b * (PB_H * TB_H);
        int pblk = r / TB_H, tcb = r - pblk * TB_H;
        pts  = hv + (size_t)b * NH * 3;  P = NH;
        tb   = d_otri + (size_t)b * FO * 6;
        hits = d_hits_h + b * NH;
        int lim = fsplits[b];                 // invalid tail is contiguous
        t0 = tcb * TCH; t1 = min(t0 + TCH, lim);
        pofs = pblk * PPB;
        if (t0 >= t1) return;                 // XOR identity: nothing to publish
    }

    int n = t1 - t0;
    // flat cooperative stage load: n*6 float4s, fully coalesced
    {
        const float4* src = tb + (size_t)t0 * 6;
        for (int i = threadIdx.x; i < n * 6; i += RTPB) s[i] = src[i];
    }

    float px[PT], py[PT], pz[PT];
    bool act[PT];
    #pragma unroll
    for (int k = 0; k < PT; k++) {
        int p = pofs + k * RTPB + threadIdx.x;
        act[k] = p < P;
        int pc = act[k] ? p : 0;
        px[k] = pts[pc*3+0]; py[k] = pts[pc*3+1]; pz[k] = pts[pc*3+2];
    }
    u64 pxp[2], pyp[2], pzp[2];
    pxp[0] = pk2(px[0], px[1]); pxp[1] = pk2(px[2], px[3]);
    pyp[0] = pk2(py[0], py[1]); pyp[1] = pk2(py[2], py[3]);
    pzp[0] = pk2(pz[0], pz[1]); pzp[1] = pk2(pz[2], pz[3]);
    const u64 ONE2  = pk2(1.0f, 1.0f);
    const u64 NEG2  = pk2(-1.0f, -1.0f);
    unsigned cnt[PT] = {0u, 0u, 0u, 0u};
    __syncthreads();

    const ulonglong2* sd = (const ulonglong2*)s;
    for (int j = 0; j < n; j++) {
        ulonglong2 A = sd[j*6+0], B = sd[j*6+1], C = sd[j*6+2];
        ulonglong2 D = sd[j*6+3], E = sd[j*6+4], F = sd[j*6+5];
        #pragma unroll
        for (int pr = 0; pr < 2; pr++) {
            u64 u = fma2(pzp[pr], B.x, B.y);
            u     = fma2(pyp[pr], A.y, u);
            u     = fma2(pxp[pr], A.x, u);
            u64 v = fma2(pzp[pr], D.x, D.y);
            v     = fma2(pyp[pr], C.y, v);
            v     = fma2(pxp[pr], C.x, v);
            u64 t = fma2(pzp[pr], F.x, F.y);
            t     = fma2(pyp[pr], E.y, t);
            t     = fma2(pxp[pr], E.x, t);
            u64 sm = add2(u, v);
            u64 w  = fma2(sm, NEG2, ONE2);       // 1 - (u+v)
            unsigned ul,uh,vl,vh,tl,th,wl,wh;
            upk2u(u,ul,uh); upk2u(v,vl,vh); upk2u(t,tl,th); upk2u(w,wl,wh);
            // hit iff all four sign bits clear; accumulate parity in MSB
            cnt[pr*2+0] ^= ~(ul | vl | tl | wl) & 0x80000000u;
            cnt[pr*2+1] ^= ~(uh | vh | th | wh) & 0x80000000u;
        }
    }
    #pragma unroll
    for (int k = 0; k < PT; k++) {
        if (act[k] && cnt[k])
            atomicXor(&hits[pofs + k * RTPB + threadIdx.x], cnt[k]);
    }
}

// ---------------------------------------------------------------------------
// Nearest neighbor, packed f32x2: candidates pre-splatted in smem,
// min over metric d' = 0.5|c|^2 - q.c.
__global__ __launch_bounds__(RTPB) void closest_fused(
        const float* __restrict__ hv, const float* __restrict__ ov,
        const int* __restrict__ vsplit) {
    __shared__ float4 s[CTCH * 2];
    int cb = blockIdx.x;
    const float* qpts; const float* cpts;
    unsigned* best; int Q, qofs, c0, c1, Svalid;
    if (cb < CBLK_A) {
        // hand queries vs valid obj candidates
        int b = cb / (CQB_H * CCH_O);
        int r = cb - b * (CQB_H * CCH_O);
        int qb = r / CCH_O, ck = r - qb * CCH_O;
        int S = vsplit[b];
        c0 = ck * CTCH; c1 = min(c0 + CTCH, S);
        if (c0 >= c1) return;
        qpts = hv + (size_t)b * NH * 3; Q = NH; Svalid = NH;
        cpts = ov + (size_t)b * NO * 3;
        best = d_best_h + b * NH;
        qofs = qb * PPB;
    } else {
        // obj queries (valid only) vs all hand candidates
        int r2 = cb - CBLK_A;
        int b = r2 / (CQB_O * CCH_H);
        int r = r2 - b * (CQB_O * CCH_H);
        int qb = r / CCH_H, ck = r - qb * CCH_H;
        c0 = ck * CTCH; c1 = min(c0 + CTCH, NH);
        qpts = ov + (size_t)b * NO * 3; Q = NO; Svalid = vsplit[b];
        cpts = hv + (size_t)b * NH * 3;
        best = d_best_o + b * NO;
        qofs = qb * PPB;
    }
    int cntc = c1 - c0;
    if (threadIdx.x < cntc) {
        const float* c = cpts + (size_t)(c0 + threadIdx.x) * 3;
        float cx = c[0], cy = c[1], cz = c[2];
        float cw = 0.5f * (cx*cx + cy*cy + cz*cz);
        s[threadIdx.x*2+0] = make_float4(cx, cx, cy, cy);
        s[threadIdx.x*2+1] = make_float4(cz, cz, cw, cw);
    }

    float qx[PT], qy[PT], qz[PT], bst[PT];
    bool act[PT];
    #pragma unroll
    for (int k = 0; k < PT; k++) {
        int q = qofs + k * RTPB + threadIdx.x;
        act[k] = (q < Q) && (q < Svalid);
        int qc = (q < Q) ? q : 0;
        qx[k] = -qpts[qc*3+0]; qy[k] = -qpts[qc*3+1]; qz[k] = -qpts[qc*3+2];
        bst[k] = BIGF;
    }
    u64 qxp[2], qyp[2], qzp[2];
    qxp[0] = pk2(qx[0], qx[1]); qxp[1] = pk2(qx[2], qx[3]);
    qyp[0] = pk2(qy[0], qy[1]); qyp[1] = pk2(qy[2], qy[3]);
    qzp[0] = pk2(qz[0], qz[1]); qzp[1] = pk2(qz[2], qz[3]);
    __syncthreads();

    const ulonglong2* sc = (const ulonglong2*)s;
    for (int j = 0; j < cntc; j++) {
        ulonglong2 C0 = sc[j*2+0], C1 = sc[j*2+1];
        #pragma unroll
        for (int pr = 0; pr < 2; pr++) {
            u64 d = fma2(qzp[pr], C1.x, C1.y);
            d     = fma2(qyp[pr], C0.y, d);
            d     = fma2(qxp[pr], C0.x, d);
            float dl, dh; upk2f(d, dl, dh);
            bst[pr*2+0] = fminf(bst[pr*2+0], dl);
            bst[pr*2+1] = fminf(bst[pr*2+1], dh);
        }
    }
    #pragma unroll
    for (int k = 0; k < PT; k++) {
        if (act[k])
            atomicMin(&best[qofs + k * RTPB + threadIdx.x], ford(bst[k]));
    }
}

// ---------------------------------------------------------------------------
// Parallel reduction: 16 slices/batch, fast tanh, partials into d_part;
// ticketed last block combines cooperatively.
__global__ void reduce_all(const float* __restrict__ hv,
                           const float* __restrict__ ov,
                           const int* __restrict__ vsplit,
                           float* __restrict__ out) {
    __shared__ float sm[8][6];
    __shared__ float fp[BATCH * 6];
    __shared__ int lastflag;
    int b  = blockIdx.x / RSL;
    int sl = blockIdx.x - b * RSL;
    int i0 = sl * RCH, i1 = min(i0 + RCH, RITEMS);
    int S = vsplit[b];
    float s1 = 0, c1 = 0, s2 = 0, c2 = 0, s3 = 0, c3 = 0;
    for (int i = i0 + threadIdx.x; i < i1; i += blockDim.x) {
        if (i < NH) {
            int n = i;
            const float* h = hv + ((size_t)b * NH + n) * 3;
            float rx = h[0]*h[0] + h[1]*h[1] + h[2]*h[2];
            float dp = funord(d_best_h[b * NH + n]);   // min(0.5*ry - zz)
            float a = sqrtf(fmaxf(fmaf(2.0f, dp, rx), 0.0f));
            float v = val25(a);
            bool ext = (d_hits_h[b * NH + n] & 0x80000000u) == 0;  // parity MSB
            if (ext) { s1 += v; c1 += 1.f; }
            else     { s2 += v; c2 += 1.f; }
        } else {
            int m = i - NH;
            if (m < S && (d_hits_o[b * NO + m] & 0x80000000u) != 0) {
                const float* o = ov + ((size_t)b * NO + m) * 3;
                float ry = o[0]*o[0] + o[1]*o[1] + o[2]*o[2];
                float dp = funord(d_best_o[b * NO + m]);
                float a = sqrtf(fmaxf(fmaf(2.0f, dp, ry), 0.0f));
                s3 += val25(a); c3 += 1.f;
            }
        }
    }
    #pragma unroll
    for (int off = 16; off; off >>= 1) {
        s1 += __shfl_down_sync(0xffffffffu, s1, off);
        c1 += __shfl_down_sync(0xffffffffu, c1, off);
        s2 += __shfl_down_sync(0xffffffffu, s2, off);
        c2 += __shfl_down_sync(0xffffffffu, c2, off);
        s3 += __shfl_down_sync(0xffffffffu, s3, off);
        c3 += __shfl_down_sync(0xffffffffu, c3, off);
    }
    int w = threadIdx.x >> 5;
    if ((threadIdx.x & 31) == 0) {
        sm[w][0] = s1; sm[w][1] = c1; sm[w][2] = s2;
        sm[w][3] = c2; sm[w][4] = s3; sm[w][5] = c3;
    }
    __syncthreads();
    if (threadIdx.x == 0) {
        for (int i = 1; i < (int)(blockDim.x >> 5); i++) {
            s1 += sm[i][0]; c1 += sm[i][1]; s2 += sm[i][2];
            c2 += sm[i][3]; s3 += sm[i][4]; c3 += sm[i][5];
        }
        atomicAdd(&d_part[b*6+0], s1); atomicAdd(&d_part[b*6+1], c1);
        atomicAdd(&d_part[b*6+2], s2); atomicAdd(&d_part[b*6+3], c2);
        atomicAdd(&d_part[b*6+4], s3); atomicAdd(&d_part[b*6+5], c3);
        __threadfence();
        unsigned t = atomicAdd(&d_tick, 1u);
        lastflag = (t == RBLKS - 1);
    }
    __syncthreads();
    if (lastflag) {
        int t = threadIdx.x;
        if (t < BATCH * 6) fp[t] = d_part[t];   // parallel gather of partials
        __syncthreads();
        if (t < BATCH) {
            float p1 = fp[t*6+1], p3 = fp[t*6+3], p5 = fp[t*6+5];
            float missed_b = (p1 > 0.f) ? fp[t*6+0] / fmaxf(p1, 1.0f) : 0.0f;
            float ph_b     = (p3 > 0.f) ? fp[t*6+2] / fmaxf(p3, 1.0f) : 0.0f;
            float po_b     = (p5 > 0.f) ? fp[t*6+4] / fmaxf(p5, 1.0f) : 0.0f;
            out[2 + t]  = missed_b;
            out[10 + t] = ph_b + po_b;
        }
        if (t == 0) {
            float Sm = 0, Cm = 0, Sh = 0, Ch = 0, So = 0, Co = 0;
            #pragma unroll
            for (int bb = 0; bb < BATCH; bb++) {
                Sm += fp[bb*6+0]; Cm += fp[bb*6+1];
                Sh += fp[bb*6+2]; Ch += fp[bb*6+3];
                So += fp[bb*6+4]; Co += fp[bb*6+5];
            }
            float missed_loss = (Cm > 0.f) ? Sm / fmaxf(Cm, 1.0f) : 0.0f;
            float ph_loss     = (Ch > 0.f) ? Sh / fmaxf(Ch, 1.0f) : 0.0f;
            float po_loss     = (Co > 0.f) ? So / fmaxf(Co, 1.0f) : 0.0f;
            out[0] = missed_loss;
            out[1] = ph_loss + po_loss;
        }
    }
}

// ---------------------------------------------------------------------------
extern "C" void kernel_launch(void* const* d_in, const int* in_sizes, int n_in,
                              void* d_out, int out_size) {
    const float* hand_verts = (const float*)d_in[0];
    const int*   hand_faces = (const int*)d_in[1];
    const float* obj_verts  = (const float*)d_in[2];
    const int*   obj_faces  = (const int*)d_in[3];
    const int*   vsplits    = (const int*)d_in[4];
    const int*   fsplits    = (const int*)d_in[5];
    float* out = (float*)d_out;

    prep_fused<<<(BATCH * (FH + FO) / 2 + 127) / 128, 128>>>(
        hand_verts, hand_faces, obj_verts, obj_faces, fsplits);
    raycast_fused<<<BLKS_O + BLKS_H, RTPB>>>(hand_verts, obj_verts, fsplits);
    closest_fused<<<CBLK_A + CBLK_B, RTPB>>>(hand_verts, obj_verts, vsplits);
    reduce_all<<<RBLKS, 256>>>(hand_verts, obj_verts, vsplits, out);
}

// round 16
// speedup vs baseline: 1.3880x; 1.0545x over previous
#include <cuda_runtime.h>

// Problem-fixed sizes (from setup_inputs)
#define BATCH 8
#define NH 778      // hand verts
#define FH 1538     // hand faces
#define NO 2000     // obj verts
#define FO 4000     // obj faces

#define TOLF    1e-7f
#define DETEPS  1e-8f   // float32(0.1 * TOL)
#define THRESH  25.0f
#define BIGF    3.4e38f

// Fixed ray direction (float32 of reference constants)
#define RDX 0.4395064455f
#define RDY 0.617598629942f
#define RDZ 0.652231566745f

// Raycast tiling
#define PT   4            // points per thread (2 packed pairs)
#define RTPB 128          // threads per block
#define PPB  (PT*RTPB)    // 512 points per block
#define TCH  64           // triangles per smem stage
#define PB_O ((NO + PPB - 1) / PPB)   // 4
#define PB_H ((NH + PPB - 1) / PPB)   // 2
#define TB_O ((FH + TCH - 1) / TCH)   // 25
#define TB_H ((FO + TCH - 1) / TCH)   // 63
#define BLKS_O (BATCH * PB_O * TB_O)  // 800
#define BLKS_H (BATCH * PB_H * TB_H)  // 1008

// Closest tiling (slot-store version: no atomics, no init)
#define CTCH 128
#define CQB_H ((NH + PPB - 1) / PPB)  // 2
#define CQB_O ((NO + PPB - 1) / PPB)  // 4
#define CCH_O ((NO + CTCH - 1) / CTCH)  // 16
#define CCH_H ((NH + CTCH - 1) / CTCH)  // 7
#define CBLK_A (BATCH * CQB_H * CCH_O)  // 256
#define CBLK_B (BATCH * CQB_O * CCH_H)  // 224
#define CBLK   (CBLK_A + CBLK_B)        // 480

// Prep tiling (2 triangles per thread)
#define PREPB ((BATCH * (FH + FO) / 2 + 127) / 128)   // 174

// Reduction tiling
#define RSL   16
#define RITEMS (NH + NO)                         // 2778
#define RCH   ((RITEMS + RSL - 1) / RSL)         // 174
#define RBLKS (BATCH * RSL)                      // 128

typedef unsigned long long u64;

// Scratch (no allocations allowed)
// Triangle data pre-splatted for f32x2: 6 float4 per triangle:
//  [0]=(nux,nux,nuy,nuy) [1]=(nuz,nuz,-cu,-cu)
//  [2]=(nvx,nvx,nvy,nvy) [3]=(nvz,nvz,-cv,-cv)
//  [4]=(ntx,ntx,nty,nty) [5]=(ntz,ntz,-ct',-ct')   (ct' has TOLF folded in)
__device__ float4   d_htri[BATCH * FH * 6];
__device__ float4   d_otri[BATCH * FO * 6];
__device__ unsigned d_hits_o[BATCH * NO];             // MSB = hit parity
__device__ unsigned d_hits_h[BATCH * NH];
__device__ float    d_best_h[BATCH * CCH_O * NH];     // per-chunk min slots
__device__ float    d_best_o[BATCH * CCH_H * NO];
__device__ float    d_part[BATCH * 6];
__device__ unsigned d_tick;

// ---- f32x2 packed helpers (sm_100+ PTX) -----------------------------------
__device__ __forceinline__ u64 pk2(float lo, float hi) {
    u64 r; asm("mov.b64 %0, {%1, %2};" : "=l"(r) : "f"(lo), "f"(hi)); return r;
}
__device__ __forceinline__ void upk2u(u64 v, unsigned &lo, unsigned &hi) {
    asm("mov.b64 {%0, %1}, %2;" : "=r"(lo), "=r"(hi) : "l"(v));
}
__device__ __forceinline__ void upk2f(u64 v, float &lo, float &hi) {
    asm("mov.b64 {%0, %1}, %2;" : "=f"(lo), "=f"(hi) : "l"(v));
}
__device__ __forceinline__ u64 fma2(u64 a, u64 b, u64 c) {
    u64 d; asm("fma.rn.f32x2 %0, %1, %2, %3;" : "=l"(d) : "l"(a), "l"(b), "l"(c));
    return d;
}
__device__ __forceinline__ u64 add2(u64 a, u64 b) {
    u64 d; asm("add.rn.f32x2 %0, %1, %2;" : "=l"(d) : "l"(a), "l"(b)); return d;
}

// Fast 25*tanh(a/25): branch-free MUFU path; a in [0, ~30] here so no overflow.
__device__ __forceinline__ float val25(float a) {
    float x = a * (1.0f / THRESH);
    float e = __expf(x + x);
    return THRESH * __fdividef(e - 1.0f, e + 1.0f);
}

// ---------------------------------------------------------------------------
// Triangle affine forms, pre-splatted; invalid/parallel -> zero coeffs with
// -ct' = -TOLF so t' < 0 -> guaranteed miss (matches reference mask).
__device__ __forceinline__ void prep_one(int i,
        const float* __restrict__ hv, const int* __restrict__ hf,
        const float* __restrict__ ov, const int* __restrict__ of,
        const int* __restrict__ fsplits) {
    const float* verts; const int* faces; float4* out;
    bool extra_valid = true;
    if (i < BATCH * FH) {
        int b = i / FH;
        verts = hv + (size_t)b * NH * 3;
        faces = hf + (size_t)i * 3;
        out   = d_htri + (size_t)i * 6;
    } else {
        int j = i - BATCH * FH;
        if (j >= BATCH * FO) return;
        int b = j / FO, f = j - b * FO;
        verts = ov + (size_t)b * NO * 3;
        faces = of + (size_t)j * 3;
        out   = d_otri + (size_t)j * 6;
        extra_valid = (f < fsplits[b]);
    }
    int i0 = faces[0], i1 = faces[1], i2 = faces[2];
    float v0x = verts[i0*3+0], v0y = verts[i0*3+1], v0z = verts[i0*3+2];
    float v1x = verts[i1*3+0], v1y = verts[i1*3+1], v1z = verts[i1*3+2];
    float v2x = verts[i2*3+0], v2y = verts[i2*3+1], v2z = verts[i2*3+2];
    float e1x = v1x - v0x, e1y = v1y - v0y, e1z = v1z - v0z;
    float e2x = v2x - v0x, e2y = v2y - v0y, e2z = v2z - v0z;
    float pvx = RDY * e2z - RDZ * e2y;
    float pvy = RDZ * e2x - RDX * e2z;
    float pvz = RDX * e2y - RDY * e2x;
    float det = e1x * pvx + e1y * pvy + e1z * pvz;
    bool ok = (fabsf(det) >= TOLF) && extra_valid;
    float inv = ok ? 1.0f / (det + DETEPS) : 0.0f;
    float nux = pvx * inv, nuy = pvy * inv, nuz = pvz * inv;
    float cu = v0x * nux + v0y * nuy + v0z * nuz;
    float wx = e1y * RDZ - e1z * RDY;
    float wy = e1z * RDX - e1x * RDZ;
    float wz = e1x * RDY - e1y * RDX;
    float nvx = wx * inv, nvy = wy * inv, nvz = wz * inv;
    float cv = v0x * nvx + v0y * nvy + v0z * nvz;
    float gx = e1y * e2z - e1z * e2y;
    float gy = e1z * e2x - e1x * e2z;
    float gz = e1x * e2y - e1y * e2x;
    float ntx = gx * inv, nty = gy * inv, ntz = gz * inv;
    float ct = v0x * ntx + v0y * nty + v0z * ntz + TOLF;  // TOLF folded in
    out[0] = make_float4(nux, nux, nuy, nuy);
    out[1] = make_float4(nuz, nuz, -cu, -cu);
    out[2] = make_float4(nvx, nvx, nvy, nvy);
    out[3] = make_float4(nvz, nvz, -cv, -cv);
    out[4] = make_float4(ntx, ntx, nty, nty);
    out[5] = make_float4(ntz, ntz, -ct, -ct);
}

// ---------------------------------------------------------------------------
// Fused launch #1: closest (slot-store) + prep (+ zeroing). The two phases
// are data-independent; closest writes only d_best slots, prep writes
// triangle forms and zeroes hits/part/tick for the later launches.
__global__ void setup_fused(
        const float* __restrict__ hv, const int* __restrict__ hf,
        const float* __restrict__ ov, const int* __restrict__ of,
        const int* __restrict__ fsplits, const int* __restrict__ vsplit) {
    int bid = blockIdx.x;
    if (bid >= CBLK) {
        // ------------- prep branch -------------
        int ptid = (bid - CBLK) * 128 + threadIdx.x;
        if (ptid < BATCH * NO) d_hits_o[ptid] = 0u;
        if (ptid < BATCH * NH) d_hits_h[ptid] = 0u;
        if (ptid < BATCH * 6)  d_part[ptid] = 0.0f;
        if (ptid == 0) d_tick = 0;
        int i0 = ptid * 2;
        prep_one(i0,     hv, hf, ov, of, fsplits);
        prep_one(i0 + 1, hv, hf, ov, of, fsplits);
        return;
    }
    // ------------- closest branch (packed f32x2, slot stores) -------------
    __shared__ float4 s[CTCH * 2];
    const float* qpts; const float* cpts;
    float* slot; int Q, qofs, c0, c1;
    if (bid < CBLK_A) {
        // hand queries vs valid obj candidates
        int b = bid / (CQB_H * CCH_O);
        int r = bid - b * (CQB_H * CCH_O);
        int qb = r / CCH_O, ck = r - qb * CCH_O;
        int S = vsplit[b];
        c0 = ck * CTCH; c1 = min(c0 + CTCH, S);
        qpts = hv + (size_t)b * NH * 3; Q = NH;
        cpts = ov + (size_t)b * NO * 3;
        slot = d_best_h + ((size_t)b * CCH_O + ck) * NH;
        qofs = qb * PPB;
    } else {
        // obj queries vs all hand candidates (all chunks valid)
        int r2 = bid - CBLK_A;
        int b = r2 / (CQB_O * CCH_H);
        int r = r2 - b * (CQB_O * CCH_H);
        int qb = r / CCH_H, ck = r - qb * CCH_H;
        c0 = ck * CTCH; c1 = min(c0 + CTCH, NH);
        qpts = ov + (size_t)b * NO * 3; Q = NO;
        cpts = hv + (size_t)b * NH * 3;
        slot = d_best_o + ((size_t)b * CCH_H + ck) * NO;
        qofs = qb * PPB;
    }
    if (c0 >= c1) {
        // dead chunk: publish neutral element for our query range
        #pragma unroll
        for (int k = 0; k < PT; k++) {
            int q = qofs + k * RTPB + threadIdx.x;
            if (q < Q) slot[q] = BIGF;
        }
        return;
    }
    int cntc = c1 - c0;
    if (threadIdx.x < cntc) {
        const float* c = cpts + (size_t)(c0 + threadIdx.x) * 3;
        float cx = c[0], cy = c[1], cz = c[2];
        float cw = 0.5f * (cx*cx + cy*cy + cz*cz);
        s[threadIdx.x*2+0] = make_float4(cx, cx, cy, cy);
        s[threadIdx.x*2+1] = make_float4(cz, cz, cw, cw);
    }
    float qx[PT], qy[PT], qz[PT], bst[PT];
    #pragma unroll
    for (int k = 0; k < PT; k++) {
        int q = qofs + k * RTPB + threadIdx.x;
        int qc = (q < Q) ? q : 0;
        qx[k] = -qpts[qc*3+0]; qy[k] = -qpts[qc*3+1]; qz[k] = -qpts[qc*3+2];
        bst[k] = BIGF;
    }
    u64 qxp[2], qyp[2], qzp[2];
    qxp[0] = pk2(qx[0], qx[1]); qxp[1] = pk2(qx[2], qx[3]);
    qyp[0] = pk2(qy[0], qy[1]); qyp[1] = pk2(qy[2], qy[3]);
    qzp[0] = pk2(qz[0], qz[1]); qzp[1] = pk2(qz[2], qz[3]);
    __syncthreads();
    const ulonglong2* sc = (const ulonglong2*)s;
    for (int j = 0; j < cntc; j++) {
        ulonglong2 C0 = sc[j*2+0], C1 = sc[j*2+1];
        #pragma unroll
        for (int pr = 0; pr < 2; pr++) {
            u64 d = fma2(qzp[pr], C1.x, C1.y);
            d     = fma2(qyp[pr], C0.y, d);
            d     = fma2(qxp[pr], C0.x, d);
            float dl, dh; upk2f(d, dl, dh);
            bst[pr*2+0] = fminf(bst[pr*2+0], dl);
            bst[pr*2+1] = fminf(bst[pr*2+1], dh);
        }
    }
    #pragma unroll
    for (int k = 0; k < PT; k++) {
        int q = qofs + k * RTPB + threadIdx.x;
        if (q < Q) slot[q] = bst[k];               // plain store, own slot
    }
}

// ---------------------------------------------------------------------------
// Parity raycast, packed f32x2: 2 point-pairs per thread, sign-bit OR for the
// hit test, LOP3 parity accumulation, atomicXor publish. TCH=64 for occupancy.
__global__ void raycast_fused(
        const float* __restrict__ hv, const float* __restrict__ ov,
        const int* __restrict__ fsplits) {
    __shared__ float4 s[TCH * 6];
    int bid = blockIdx.x;
    const float* pts; const float4* tb; unsigned* hits;
    int P, t0, t1, pofs;
    if (bid < BLKS_O) {
        int b = bid / (PB_O * TB_O);
        int r = bid - b * (PB_O * TB_O);
        int pblk = r / TB_O, tcb = r - pblk * TB_O;
        pts  = ov + (size_t)b * NO * 3;  P = NO;
        tb   = d_htri + (size_t)b * FH * 6;
        hits = d_hits_o + b * NO;
        t0 = tcb * TCH; t1 = min(t0 + TCH, FH);
        pofs = pblk * PPB;
    } else {
        int r2 = bid - BLKS_O;
        int b = r2 / (PB_H * TB_H);
        int r = r2 - b * (PB_H * TB_H);
        int pblk = r / TB_H, tcb = r - pblk * TB_H;
        pts  = hv + (size_t)b * NH * 3;  P = NH;
        tb   = d_otri + (size_t)b * FO * 6;
        hits = d_hits_h + b * NH;
        int lim = fsplits[b];                 // invalid tail is contiguous
        t0 = tcb * TCH; t1 = min(t0 + TCH, lim);
        pofs = pblk * PPB;
        if (t0 >= t1) return;                 // XOR identity: nothing to publish
    }

    int n = t1 - t0;
    // flat cooperative stage load: n*6 float4s, fully coalesced
    {
        const float4* src = tb + (size_t)t0 * 6;
        for (int i = threadIdx.x; i < n * 6; i += RTPB) s[i] = src[i];
    }

    float px[PT], py[PT], pz[PT];
    bool act[PT];
    #pragma unroll
    for (int k = 0; k < PT; k++) {
        int p = pofs + k * RTPB + threadIdx.x;
        act[k] = p < P;
        int pc = act[k] ? p : 0;
        px[k] = pts[pc*3+0]; py[k] = pts[pc*3+1]; pz[k] = pts[pc*3+2];
    }
    u64 pxp[2], pyp[2], pzp[2];
    pxp[0] = pk2(px[0], px[1]); pxp[1] = pk2(px[2], px[3]);
    pyp[0] = pk2(py[0], py[1]); pyp[1] = pk2(py[2], py[3]);
    pzp[0] = pk2(pz[0], pz[1]); pzp[1] = pk2(pz[2], pz[3]);
    const u64 ONE2  = pk2(1.0f, 1.0f);
    const u64 NEG2  = pk2(-1.0f, -1.0f);
    unsigned cnt[PT] = {0u, 0u, 0u, 0u};
    __syncthreads();

    const ulonglong2* sd = (const ulonglong2*)s;
    for (int j = 0; j < n; j++) {
        ulonglong2 A = sd[j*6+0], B = sd[j*6+1], C = sd[j*6+2];
        ulonglong2 D = sd[j*6+3], E = sd[j*6+4], F = sd[j*6+5];
        #pragma unroll
        for (int pr = 0; pr < 2; pr++) {
            u64 u = fma2(pzp[pr], B.x, B.y);
            u     = fma2(pyp[pr], A.y, u);
            u     = fma2(pxp[pr], A.x, u);
            u64 v = fma2(pzp[pr], D.x, D.y);
            v     = fma2(pyp[pr], C.y, v);
            v     = fma2(pxp[pr], C.x, v);
            u64 t = fma2(pzp[pr], F.x, F.y);
            t     = fma2(pyp[pr], E.y, t);
            t     = fma2(pxp[pr], E.x, t);
            u64 sm = add2(u, v);
            u64 w  = fma2(sm, NEG2, ONE2);       // 1 - (u+v)
            unsigned ul,uh,vl,vh,tl,th,wl,wh;
            upk2u(u,ul,uh); upk2u(v,vl,vh); upk2u(t,tl,th); upk2u(w,wl,wh);
            // hit iff all four sign bits clear; accumulate parity in MSB
            cnt[pr*2+0] ^= ~(ul | vl | tl | wl) & 0x80000000u;
            cnt[pr*2+1] ^= ~(uh | vh | th | wh) & 0x80000000u;
        }
    }
    #pragma unroll
    for (int k = 0; k < PT; k++) {
        if (act[k] && cnt[k])
            atomicXor(&hits[pofs + k * RTPB + threadIdx.x], cnt[k]);
    }
}

// ---------------------------------------------------------------------------
// Parallel reduction: 16 slices/batch, folds per-chunk best slots (unrolled
// independent loads), fast tanh, partials into d_part; ticketed last block
// combines cooperatively.
__global__ void reduce_all(const float* __restrict__ hv,
                           const float* __restrict__ ov,
                           const int* __restrict__ vsplit,
                           float* __restrict__ out) {
    __shared__ float sm[8][6];
    __shared__ float fp[BATCH * 6];
    __shared__ int lastflag;
    int b  = blockIdx.x / RSL;
    int sl = blockIdx.x - b * RSL;
    int i0 = sl * RCH, i1 = min(i0 + RCH, RITEMS);
    int S = vsplit[b];
    float s1 = 0, c1 = 0, s2 = 0, c2 = 0, s3 = 0, c3 = 0;
    for (int i = i0 + threadIdx.x; i < i1; i += blockDim.x) {
        if (i < NH) {
            int n = i;
            const float* h = hv + ((size_t)b * NH + n) * 3;
            float rx = h[0]*h[0] + h[1]*h[1] + h[2]*h[2];
            float dp = BIGF;
            #pragma unroll
            for (int c = 0; c < CCH_O; c++)
                dp = fminf(dp, d_best_h[((size_t)b * CCH_O + c) * NH + n]);
            float a = sqrtf(fmaxf(fmaf(2.0f, dp, rx), 0.0f));
            float v = val25(a);
            bool ext = (d_hits_h[b * NH + n] & 0x80000000u) == 0;  // parity MSB
            if (ext) { s1 += v; c1 += 1.f; }
            else     { s2 += v; c2 += 1.f; }
        } else {
            int m = i - NH;
            if (m < S && (d_hits_o[b * NO + m] & 0x80000000u) != 0) {
                const float* o = ov + ((size_t)b * NO + m) * 3;
                float ry = o[0]*o[0] + o[1]*o[1] + o[2]*o[2];
                float dp = BIGF;
                #pragma unroll
                for (int c = 0; c < CCH_H; c++)
                    dp = fminf(dp, d_best_o[((size_t)b * CCH_H + c) * NO + m]);
                float a = sqrtf(fmaxf(fmaf(2.0f, dp, ry), 0.0f));
                s3 += val25(a); c3 += 1.f;
            }
        }
    }
    #pragma unroll
    for (int off = 16; off; off >>= 1) {
        s1 += __shfl_down_sync(0xffffffffu, s1, off);
        c1 += __shfl_down_sync(0xffffffffu, c1, off);
        s2 += __shfl_down_sync(0xffffffffu, s2, off);
        c2 += __shfl_down_sync(0xffffffffu, c2, off);
        s3 += __shfl_down_sync(0xffffffffu, s3, off);
        c3 += __shfl_down_sync(0xffffffffu, c3, off);
    }
    int w = threadIdx.x >> 5;
    if ((threadIdx.x & 31) == 0) {
        sm[w][0] = s1; sm[w][1] = c1; sm[w][2] = s2;
        sm[w][3] = c2; sm[w][4] = s3; sm[w][5] = c3;
    }
    __syncthreads();
    if (threadIdx.x == 0) {
        for (int i = 1; i < (int)(blockDim.x >> 5); i++) {
            s1 += sm[i][0]; c1 += sm[i][1]; s2 += sm[i][2];
            c2 += sm[i][3]; s3 += sm[i][4]; c3 += sm[i][5];
        }
        atomicAdd(&d_part[b*6+0], s1); atomicAdd(&d_part[b*6+1], c1);
        atomicAdd(&d_part[b*6+2], s2); atomicAdd(&d_part[b*6+3], c2);
        atomicAdd(&d_part[b*6+4], s3); atomicAdd(&d_part[b*6+5], c3);
        __threadfence();
        unsigned t = atomicAdd(&d_tick, 1u);
        lastflag = (t == RBLKS - 1);
    }
    __syncthreads();
    if (lastflag) {
        int t = threadIdx.x;
        if (t < BATCH * 6) fp[t] = d_part[t];   // parallel gather of partials
        __syncthreads();
        if (t < BATCH) {
            float p1 = fp[t*6+1], p3 = fp[t*6+3], p5 = fp[t*6+5];
            float missed_b = (p1 > 0.f) ? fp[t*6+0] / fmaxf(p1, 1.0f) : 0.0f;
            float ph_b     = (p3 > 0.f) ? fp[t*6+2] / fmaxf(p3, 1.0f) : 0.0f;
            float po_b     = (p5 > 0.f) ? fp[t*6+4] / fmaxf(p5, 1.0f) : 0.0f;
            out[2 + t]  = missed_b;
            out[10 + t] = ph_b + po_b;
        }
        if (t == 0) {
            float Sm = 0, Cm = 0, Sh = 0, Ch = 0, So = 0, Co = 0;
            #pragma unroll
            for (int bb = 0; bb < BATCH; bb++) {
                Sm += fp[bb*6+0]; Cm += fp[bb*6+1];
                Sh += fp[bb*6+2]; Ch += fp[bb*6+3];
                So += fp[bb*6+4]; Co += fp[bb*6+5];
            }
            float missed_loss = (Cm > 0.f) ? Sm / fmaxf(Cm, 1.0f) : 0.0f;
            float ph_loss     = (Ch > 0.f) ? Sh / fmaxf(Ch, 1.0f) : 0.0f;
            float po_loss     = (Co > 0.f) ? So / fmaxf(Co, 1.0f) : 0.0f;
            out[0] = missed_loss;
            out[1] = ph_loss + po_loss;
        }
    }
}

// ---------------------------------------------------------------------------
extern "C" void kernel_launch(void* const* d_in, const int* in_sizes, int n_in,
                              void* d_out, int out_size) {
    const float* hand_verts = (const float*)d_in[0];
    const int*   hand_faces = (const int*)d_in[1];
    const float* obj_verts  = (const float*)d_in[2];
    const int*   obj_faces  = (const int*)d_in[3];
    const int*   vsplits    = (const int*)d_in[4];
    const int*   fsplits    = (const int*)d_in[5];
    float* out = (float*)d_out;

    setup_fused<<<CBLK + PREPB, RTPB>>>(
        hand_verts, hand_faces, obj_verts, obj_faces, fsplits, vsplits);
    raycast_fused<<<BLKS_O + BLKS_H, RTPB>>>(hand_verts, obj_verts, fsplits);
    reduce_all<<<RBLKS, 256>>>(hand_verts, obj_verts, vsplits, out);
}